// round 12
// baseline (speedup 1.0000x reference)
#include <cuda_runtime.h>

// Problem constants (fixed shapes from reference)
constexpr int Bb   = 8;
constexpr int Tt   = 12;
constexpr int Nn   = 1500;
constexpr int HID_ = 64;
constexpr int BN   = Bb * Nn;     // 12000
constexpr int SPB  = 32;          // sequences per LSTM block
constexpr int SPBP = 36;          // padded row
constexpr int NW   = 47;          // ceil(1500/32) adjacency bitmask words per row
constexpr int ZCH  = 4;           // attention j-splits (grid fits one wave)
constexpr int JRANGE = 384;       // j per split (multiple of 64; last split clamps)
constexpr int TI   = 128;         // attention i-tile (4 rows per thread)

#define DEVINL __device__ __forceinline__
typedef unsigned long long ull;

// ---------------- scratch (device globals; no allocation allowed) ----------
__device__ __align__(16) float d_Wp0[64 * 256];    // [j][u][gate] packed, layer0 Whh
__device__ __align__(16) float d_Wp1i[64 * 256];   // layer1 Wih packed
__device__ __align__(16) float d_Wp1h[64 * 256];   // layer1 Whh packed
__device__ float d_b0[256], d_b1[256];
__device__ __align__(16) float d_g0WT[64 * 64], d_g1WT[64 * 64];
__device__ __align__(16) float d_h [BN * 64];      // LSTM out / GAT1 out
__device__ __align__(16) float d_h2[BN * 64];      // GAT0 out
__device__ __align__(16) float d_hp[BN * 64];      // projected features (per layer)
__device__ __align__(16) float4 d_esv[BN * 4];     // (exp(es), exp(0.2es), es, 0)
__device__ __align__(16) float4 d_edv[BN * 4];     // (exp(ed), exp(0.2ed), ed, 0)
__device__ unsigned d_adjb[Nn * NW];               // bitpacked adjacency
__device__ __align__(16) float d_pacc[ZCH * BN * 64];
__device__ float d_pss[ZCH * BN * 4];

// HW tanh (MUFU.TANH, sm_75+): 1 MUFU op vs exp+add+rcp chain
DEVINL float ftanh(float z) {
    float r;
    asm("tanh.approx.f32 %0, %1;" : "=f"(r) : "f"(z));
    return r;
}
DEVINL float fsig(float z)  { return fmaf(ftanh(0.5f * z), 0.5f, 0.5f); }

// ---- packed fp32x2 helpers -------------------------------------------------
DEVINL ull dup2(float x) {
    ull r; unsigned xi = __float_as_uint(x);
    asm("mov.b64 %0, {%1, %1};" : "=l"(r) : "r"(xi));
    return r;
}
DEVINL ull pk2(float lo, float hi) {
    ull r;
    asm("mov.b64 %0, {%1, %2};" : "=l"(r)
        : "r"(__float_as_uint(lo)), "r"(__float_as_uint(hi)));
    return r;
}
DEVINL ull ffma2(ull a, ull b, ull c) {
    ull d;
    asm("fma.rn.f32x2 %0, %1, %2, %3;" : "=l"(d) : "l"(a), "l"(b), "l"(c));
    return d;
}
DEVINL float2 unpk(ull v) {
    unsigned lo, hi;
    asm("mov.b64 {%0, %1}, %2;" : "=r"(lo), "=r"(hi) : "l"(v));
    return make_float2(__uint_as_float(lo), __uint_as_float(hi));
}

// ---------------- prep: packed transposes + fused biases + adj bitpack ------
__global__ void prep_kernel(const float* __restrict__ adj_,
                            const float* __restrict__ Whh0,
                            const float* __restrict__ bih0, const float* __restrict__ bhh0,
                            const float* __restrict__ Wih1, const float* __restrict__ Whh1,
                            const float* __restrict__ bih1, const float* __restrict__ bhh1,
                            const float* __restrict__ g0W,  const float* __restrict__ g1W)
{
    const int* __restrict__ adj = (const int*)adj_;
    int idx = blockIdx.x * blockDim.x + threadIdx.x;
    if (idx < 16384) {
        int r = idx >> 6, j = idx & 63;
        int g = r >> 6, u = r & 63;
        int p = j * 256 + u * 4 + g;
        d_Wp0 [p] = Whh0[idx];
        d_Wp1i[p] = Wih1[idx];
        d_Wp1h[p] = Whh1[idx];
    }
    if (idx < 256) {
        d_b0[idx] = bih0[idx] + bhh0[idx];
        d_b1[idx] = bih1[idx] + bhh1[idx];
    }
    if (idx < 4096) {
        int o = idx >> 6, k = idx & 63;
        d_g0WT[k * 64 + o] = g0W[idx];
        d_g1WT[k * 64 + o] = g1W[idx];
    }
    if (idx < Nn * NW) {
        int i = idx / NW, w = idx % NW;
        unsigned m = 0;
        int jb = w * 32;
#pragma unroll 8
        for (int b = 0; b < 32; ++b) {
            int j = jb + b;
            if (j < Nn && adj[i * Nn + j] > 0) m |= (1u << b);
        }
        d_adjb[idx] = m;
    }
}

// ---------------- 2-layer LSTM (fp32x2, float4 weights + reg-dup) -----------
__global__ __launch_bounds__(256) void lstm_kernel(
    const float* __restrict__ x, const float* __restrict__ Wih0)
{
    __shared__ __align__(16) float xs[Tt][SPB];
    __shared__ __align__(16) float h0s[2][HID_][SPBP];
    __shared__ __align__(16) float h1s[2][HID_][SPBP];

    const int tid = threadIdx.x;
    const int u   = tid & 63;
    const int sg  = tid >> 6;
    const int sbase = sg * 8;
    const int bn0 = blockIdx.x * SPB;

    for (int idx = tid; idx < Tt * SPB; idx += 256) {
        int tt = idx / SPB, s = idx % SPB;
        int bn = bn0 + s;
        int b = bn / Nn, n = bn % Nn;
        xs[tt][s] = x[(b * Tt + tt) * Nn + n];
    }
    for (int idx = tid; idx < HID_ * SPBP; idx += 256) {
        (&h0s[0][0][0])[idx] = 0.f;
        (&h1s[0][0][0])[idx] = 0.f;
    }

    float c0[8], c1[8];
#pragma unroll
    for (int s = 0; s < 8; ++s) { c0[s] = 0.f; c1[s] = 0.f; }

    const ull wi0_i2 = dup2(Wih0[u]),       wi0_f2 = dup2(Wih0[64 + u]);
    const ull wi0_g2 = dup2(Wih0[128 + u]), wi0_o2 = dup2(Wih0[192 + u]);
    const ull b0_i2 = dup2(d_b0[u]), b0_f2 = dup2(d_b0[64 + u]);
    const ull b0_g2 = dup2(d_b0[128 + u]), b0_o2 = dup2(d_b0[192 + u]);
    const ull b1_i2 = dup2(d_b1[u]), b1_f2 = dup2(d_b1[64 + u]);
    const ull b1_g2 = dup2(d_b1[128 + u]), b1_o2 = dup2(d_b1[192 + u]);

    const float4* __restrict__ Wp0  = (const float4*)&d_Wp0 [u * 4];
    const float4* __restrict__ Wp1i = (const float4*)&d_Wp1i[u * 4];
    const float4* __restrict__ Wp1h = (const float4*)&d_Wp1h[u * 4];

    __syncthreads();

    float h1v[8];
    for (int t = 0; t < Tt; ++t) {
        const int cur = t & 1, nxt = cur ^ 1;
        ull ai2[4], af2[4], ag2[4], ao2[4];
        // ---- layer 0 init from x ----
        {
            ulonglong2 xA = *(const ulonglong2*)&xs[t][sbase];
            ulonglong2 xB = *(const ulonglong2*)&xs[t][sbase + 4];
            ull xv2[4] = {xA.x, xA.y, xB.x, xB.y};
#pragma unroll
            for (int p = 0; p < 4; ++p) {
                ai2[p] = ffma2(wi0_i2, xv2[p], b0_i2);
                af2[p] = ffma2(wi0_f2, xv2[p], b0_f2);
                ag2[p] = ffma2(wi0_g2, xv2[p], b0_g2);
                ao2[p] = ffma2(wi0_o2, xv2[p], b0_o2);
            }
        }
#pragma unroll 4
        for (int j = 0; j < HID_; ++j) {
            float4 w = Wp0[j * 64];
            ull wx = dup2(w.x), wy = dup2(w.y), wz = dup2(w.z), ww = dup2(w.w);
            ulonglong2 hA = *(const ulonglong2*)&h0s[cur][j][sbase];
            ulonglong2 hB = *(const ulonglong2*)&h0s[cur][j][sbase + 4];
            ull hv2[4] = {hA.x, hA.y, hB.x, hB.y};
#pragma unroll
            for (int p = 0; p < 4; ++p) {
                ai2[p] = ffma2(wx, hv2[p], ai2[p]);
                af2[p] = ffma2(wy, hv2[p], af2[p]);
                ag2[p] = ffma2(wz, hv2[p], ag2[p]);
                ao2[p] = ffma2(ww, hv2[p], ao2[p]);
            }
        }
        float h0v[8];
#pragma unroll
        for (int p = 0; p < 4; ++p) {
            float2 vi = unpk(ai2[p]), vf = unpk(af2[p]);
            float2 vg = unpk(ag2[p]), vo = unpk(ao2[p]);
            int s0 = 2 * p, s1 = 2 * p + 1;
            c0[s0] = fmaf(fsig(vf.x), c0[s0], fsig(vi.x) * ftanh(vg.x));
            h0v[s0] = fsig(vo.x) * ftanh(c0[s0]);
            c0[s1] = fmaf(fsig(vf.y), c0[s1], fsig(vi.y) * ftanh(vg.y));
            h0v[s1] = fsig(vo.y) * ftanh(c0[s1]);
        }
#pragma unroll
        for (int s = 0; s < 8; ++s) h0s[nxt][u][sbase + s] = h0v[s];
        __syncthreads();

        // ---- layer 1 ----
#pragma unroll
        for (int p = 0; p < 4; ++p) {
            ai2[p] = b1_i2; af2[p] = b1_f2; ag2[p] = b1_g2; ao2[p] = b1_o2;
        }
#pragma unroll 4
        for (int j = 0; j < HID_; ++j) {
            float4 w = Wp1i[j * 64];
            ull wx = dup2(w.x), wy = dup2(w.y), wz = dup2(w.z), ww = dup2(w.w);
            ulonglong2 hA = *(const ulonglong2*)&h0s[nxt][j][sbase];
            ulonglong2 hB = *(const ulonglong2*)&h0s[nxt][j][sbase + 4];
            ull hv2[4] = {hA.x, hA.y, hB.x, hB.y};
#pragma unroll
            for (int p = 0; p < 4; ++p) {
                ai2[p] = ffma2(wx, hv2[p], ai2[p]);
                af2[p] = ffma2(wy, hv2[p], af2[p]);
                ag2[p] = ffma2(wz, hv2[p], ag2[p]);
                ao2[p] = ffma2(ww, hv2[p], ao2[p]);
            }
        }
#pragma unroll 4
        for (int j = 0; j < HID_; ++j) {
            float4 w = Wp1h[j * 64];
            ull wx = dup2(w.x), wy = dup2(w.y), wz = dup2(w.z), ww = dup2(w.w);
            ulonglong2 hA = *(const ulonglong2*)&h1s[cur][j][sbase];
            ulonglong2 hB = *(const ulonglong2*)&h1s[cur][j][sbase + 4];
            ull hv2[4] = {hA.x, hA.y, hB.x, hB.y};
#pragma unroll
            for (int p = 0; p < 4; ++p) {
                ai2[p] = ffma2(wx, hv2[p], ai2[p]);
                af2[p] = ffma2(wy, hv2[p], af2[p]);
                ag2[p] = ffma2(wz, hv2[p], ag2[p]);
                ao2[p] = ffma2(ww, hv2[p], ao2[p]);
            }
        }
#pragma unroll
        for (int p = 0; p < 4; ++p) {
            float2 vi = unpk(ai2[p]), vf = unpk(af2[p]);
            float2 vg = unpk(ag2[p]), vo = unpk(ao2[p]);
            int s0 = 2 * p, s1 = 2 * p + 1;
            c1[s0] = fmaf(fsig(vf.x), c1[s0], fsig(vi.x) * ftanh(vg.x));
            h1v[s0] = fsig(vo.x) * ftanh(c1[s0]);
            c1[s1] = fmaf(fsig(vf.y), c1[s1], fsig(vi.y) * ftanh(vg.y));
            h1v[s1] = fsig(vo.y) * ftanh(c1[s1]);
        }
#pragma unroll
        for (int s = 0; s < 8; ++s) h1s[nxt][u][sbase + s] = h1v[s];
        __syncthreads();
    }

#pragma unroll
    for (int s = 0; s < 8; ++s)
        d_h[(bn0 + sbase + s) * 64 + u] = h1v[s];
}

// ---------------- GAT projection + factorized attention exponentials -------
template <int LAYER>
__global__ __launch_bounds__(256) void gat_proj_kernel(
    const float* __restrict__ asrc, const float* __restrict__ adst)
{
    const float* __restrict__ hin = (LAYER == 0) ? d_h : d_h2;
    const float* __restrict__ WT  = (LAYER == 0) ? d_g0WT : d_g1WT;

    const int t  = threadIdx.x;
    const int o  = t & 63;
    const int lo = t >> 6;
    const int bn = blockIdx.x * 4 + lo;

    __shared__ float hs[4][64];
    hs[lo][o] = hin[bn * 64 + o];
    __syncthreads();

    float acc = 0.f;
#pragma unroll
    for (int k = 0; k < 64; ++k)
        acc = fmaf(hs[lo][k], WT[k * 64 + o], acc);

    d_hp[bn * 64 + o] = acc;

    float vs = acc * asrc[o];
    float vd = acc * adst[o];
#pragma unroll
    for (int off = 8; off > 0; off >>= 1) {
        vs += __shfl_down_sync(0xffffffffu, vs, off, 16);
        vd += __shfl_down_sync(0xffffffffu, vd, off, 16);
    }
    if ((o & 15) == 0) {
        int hh = o >> 4;
        d_esv[bn * 4 + hh] = make_float4(__expf(vs), __expf(0.2f * vs), vs, 0.f);
        d_edv[bn * 4 + hh] = make_float4(__expf(vd), __expf(0.2f * vd), vd, 0.f);
    }
}

// ---------------- GAT attention aggregate (4-way j-split, 4 rows/thread) ----
// block: 128 threads = 32 rslots x 4 heads; each thread owns 4 rows
// grid: (ceil(N/128), B, ZCH) = 384 blocks -> fits one resident wave
__global__ __launch_bounds__(128) void gat_attn_kernel()
{
    constexpr int JC = 64;
    const int b  = blockIdx.y;
    const int z  = blockIdx.z;
    const int i0 = blockIdx.x * TI;
    const int t  = threadIdx.x;
    const int h  = t & 3;
    const int rs = t >> 2;

    float* __restrict__ pacc = d_pacc + z * (BN * 64);
    float* __restrict__ pss  = d_pss  + z * (BN * 4);

    __shared__ __align__(16) float4 hps4[JC][4][5];  // 20 KB, padded per head
    __shared__ __align__(16) float4 edvs[JC][4];     // 4 KB
    __shared__ unsigned adjw[TI][2];                 // 1 KB

    ull acc2[4][8];
#pragma unroll
    for (int r = 0; r < 4; ++r)
#pragma unroll
        for (int d = 0; d < 8; ++d) acc2[r][d] = 0ull;
    ull ssum01 = 0ull, ssum23 = 0ull;
    const ull one2 = dup2(1.f);

    int   irow[4];
    float esA[4], esB[4], esr[4];
#pragma unroll
    for (int r = 0; r < 4; ++r) {
        irow[r] = i0 + rs + 32 * r;
        float4 ev = make_float4(0.f, 0.f, 0.f, 0.f);
        if (irow[r] < Nn) ev = d_esv[(b * Nn + irow[r]) * 4 + h];
        esA[r] = ev.x; esB[r] = ev.y; esr[r] = ev.z;
    }

    const int jbeg = z * JRANGE;
    const int jend = min(jbeg + JRANGE, Nn);

    for (int j0 = jbeg; j0 < jend; j0 += JC) {
        __syncthreads();
        for (int idx = t; idx < JC * 16; idx += 128) {
            int jj = idx >> 4, k4 = idx & 15;
            int j = j0 + jj;
            float4 v = make_float4(0.f, 0.f, 0.f, 0.f);
            if (j < Nn) v = ((const float4*)d_hp)[(b * Nn + j) * 16 + k4];
            hps4[jj][k4 >> 2][k4 & 3] = v;
        }
        for (int idx = t; idx < JC * 4; idx += 128) {
            int jj = idx >> 2, hh = idx & 3;
            int j = j0 + jj;
            float4 v = make_float4(0.f, 0.f, 0.f, 0.f);
            if (j < Nn) v = d_edv[(b * Nn + j) * 4 + hh];
            edvs[jj][hh] = v;
        }
        {
            int i = i0 + t;
            int w0 = j0 >> 5;
#pragma unroll
            for (int w = 0; w < 2; ++w) {
                unsigned m = 0;
                if (i < Nn && (w0 + w) < NW) m = d_adjb[i * NW + w0 + w];
                adjw[t][w] = m;
            }
        }
        __syncthreads();

#pragma unroll
        for (int w = 0; w < 2; ++w) {
            unsigned m0 = adjw[rs][w];
            unsigned m1 = adjw[rs + 32][w];
            unsigned m2 = adjw[rs + 64][w];
            unsigned m3 = adjw[rs + 96][w];
            const int jjb = w * 32;
#pragma unroll 2
            for (int bp = 0; bp < 32; ++bp) {
                const int jj = jjb + bp;
                float4 ed = edvs[jj][h];
                const ulonglong2* q = (const ulonglong2*)&hps4[jj][h][0];
                ulonglong2 qa = q[0], qb = q[1];

                float p[4];
                {
                    float e0 = esr[0] + ed.z;
                    float s0 = ((e0 > 0.f) ? esA[0] : esB[0]) * ((e0 > 0.f) ? ed.x : ed.y);
                    p[0] = (m0 & (1u << bp)) ? s0 : 0.f;
                    float e1 = esr[1] + ed.z;
                    float s1 = ((e1 > 0.f) ? esA[1] : esB[1]) * ((e1 > 0.f) ? ed.x : ed.y);
                    p[1] = (m1 & (1u << bp)) ? s1 : 0.f;
                    float e2 = esr[2] + ed.z;
                    float s2 = ((e2 > 0.f) ? esA[2] : esB[2]) * ((e2 > 0.f) ? ed.x : ed.y);
                    p[2] = (m2 & (1u << bp)) ? s2 : 0.f;
                    float e3 = esr[3] + ed.z;
                    float s3 = ((e3 > 0.f) ? esA[3] : esB[3]) * ((e3 > 0.f) ? ed.x : ed.y);
                    p[3] = (m3 & (1u << bp)) ? s3 : 0.f;
                }
                ssum01 = ffma2(pk2(p[0], p[1]), one2, ssum01);
                ssum23 = ffma2(pk2(p[2], p[3]), one2, ssum23);

                ull pp[4] = {dup2(p[0]), dup2(p[1]), dup2(p[2]), dup2(p[3])};
#pragma unroll
                for (int r = 0; r < 4; ++r) {
                    acc2[r][0] = ffma2(pp[r], qa.x, acc2[r][0]);
                    acc2[r][1] = ffma2(pp[r], qa.y, acc2[r][1]);
                    acc2[r][2] = ffma2(pp[r], qb.x, acc2[r][2]);
                    acc2[r][3] = ffma2(pp[r], qb.y, acc2[r][3]);
                }
                ulonglong2 qc = *(const ulonglong2*)&hps4[jj][h][2];
                ulonglong2 qd = *(const ulonglong2*)&hps4[jj][h][3];
#pragma unroll
                for (int r = 0; r < 4; ++r) {
                    acc2[r][4] = ffma2(pp[r], qc.x, acc2[r][4]);
                    acc2[r][5] = ffma2(pp[r], qc.y, acc2[r][5]);
                    acc2[r][6] = ffma2(pp[r], qd.x, acc2[r][6]);
                    acc2[r][7] = ffma2(pp[r], qd.y, acc2[r][7]);
                }
            }
        }
    }

    float2 s01 = unpk(ssum01), s23 = unpk(ssum23);
    float ssum[4] = {s01.x, s01.y, s23.x, s23.y};
#pragma unroll
    for (int r = 0; r < 4; ++r) {
        if (irow[r] < Nn) {
            int bn = b * Nn + irow[r];
            pss[bn * 4 + h] = ssum[r];
            ulonglong2* dst = (ulonglong2*)&pacc[bn * 64 + h * 16];
#pragma unroll
            for (int k = 0; k < 4; ++k)
                dst[k] = make_ulonglong2(acc2[r][2 * k], acc2[r][2 * k + 1]);
        }
    }
}

// ---------------- combine j-split partials, normalize, ReLU -----------------
template <int LAYER>
__global__ __launch_bounds__(256) void gat_combine_kernel()
{
    float* __restrict__ hout = (LAYER == 0) ? d_h2 : d_h;
    int idx = blockIdx.x * 256 + threadIdx.x;      // over BN*16 float4s
    if (idx >= BN * 16) return;
    int bn = idx >> 4;
    int f4 = idx & 15;
    int h  = f4 >> 2;
    float s = 0.f;
#pragma unroll
    for (int z = 0; z < ZCH; ++z) s += d_pss[z * (BN * 4) + bn * 4 + h];
    float inv = (s > 0.f) ? __fdividef(1.f, s) : 0.f;
    float4 a = make_float4(0.f, 0.f, 0.f, 0.f);
#pragma unroll
    for (int z = 0; z < ZCH; ++z) {
        float4 v = ((const float4*)(d_pacc + z * (BN * 64)))[idx];
        a.x += v.x; a.y += v.y; a.z += v.z; a.w += v.w;
    }
    float4 v;
    v.x = fmaxf(a.x * inv, 0.f);
    v.y = fmaxf(a.y * inv, 0.f);
    v.z = fmaxf(a.z * inv, 0.f);
    v.w = fmaxf(a.w * inv, 0.f);
    ((float4*)hout)[idx] = v;
}

// ---------------- output head: (B,N,64) @ (3,64)^T -> (B,3,N) ---------------
__global__ __launch_bounds__(256) void out_kernel(
    const float* __restrict__ outW, const float* __restrict__ outb,
    float* __restrict__ out)
{
    int gw   = (blockIdx.x * blockDim.x + threadIdx.x) >> 5;
    int lane = threadIdx.x & 31;
    if (gw >= BN) return;
    float ha = d_h[gw * 64 + lane];
    float hb = d_h[gw * 64 + 32 + lane];
    int b = gw / Nn, n = gw % Nn;
#pragma unroll
    for (int o = 0; o < 3; ++o) {
        float p = fmaf(ha, outW[o * 64 + lane], hb * outW[o * 64 + 32 + lane]);
#pragma unroll
        for (int off = 16; off > 0; off >>= 1)
            p += __shfl_down_sync(0xffffffffu, p, off);
        if (lane == 0)
            out[b * 3 * Nn + o * Nn + n] = p + outb[o];
    }
}

// ---------------- launch ----------------------------------------------------
extern "C" void kernel_launch(void* const* d_in, const int* in_sizes, int n_in,
                              void* d_out, int out_size)
{
    const float* x     = (const float*)d_in[0];
    const float* adj   = (const float*)d_in[1];   // int32 payload, cast inside prep
    const float* Wih0  = (const float*)d_in[2];
    const float* Whh0  = (const float*)d_in[3];
    const float* bih0  = (const float*)d_in[4];
    const float* bhh0  = (const float*)d_in[5];
    const float* Wih1  = (const float*)d_in[6];
    const float* Whh1  = (const float*)d_in[7];
    const float* bih1  = (const float*)d_in[8];
    const float* bhh1  = (const float*)d_in[9];
    const float* g0W   = (const float*)d_in[10];
    const float* g0as  = (const float*)d_in[11];
    const float* g0ad  = (const float*)d_in[12];
    const float* g1W   = (const float*)d_in[13];
    const float* g1as  = (const float*)d_in[14];
    const float* g1ad  = (const float*)d_in[15];
    const float* outW  = (const float*)d_in[16];
    const float* outb  = (const float*)d_in[17];
    float* out = (float*)d_out;

    prep_kernel<<<(Nn * NW + 255) / 256, 256>>>(adj, Whh0, bih0, bhh0,
                                                Wih1, Whh1, bih1, bhh1, g0W, g1W);
    lstm_kernel<<<BN / SPB, 256>>>(x, Wih0);

    dim3 agrid((Nn + TI - 1) / TI, Bb, ZCH);

    gat_proj_kernel<0><<<BN / 4, 256>>>(g0as, g0ad);
    gat_attn_kernel<<<agrid, 128>>>();
    gat_combine_kernel<0><<<(BN * 16 + 255) / 256, 256>>>();

    gat_proj_kernel<1><<<BN / 4, 256>>>(g1as, g1ad);
    gat_attn_kernel<<<agrid, 128>>>();
    gat_combine_kernel<1><<<(BN * 16 + 255) / 256, 256>>>();

    out_kernel<<<(BN * 32 + 255) / 256, 256>>>(outW, outb, out);
}

// round 14
// speedup vs baseline: 1.6181x; 1.6181x over previous
#include <cuda_runtime.h>

// Problem constants (fixed shapes from reference)
constexpr int Bb   = 8;
constexpr int Tt   = 12;
constexpr int Nn   = 1500;
constexpr int HID_ = 64;
constexpr int BN   = Bb * Nn;     // 12000
constexpr int SPB  = 32;          // sequences per LSTM block
constexpr int SPBP = 36;          // padded row
constexpr int NW   = 47;          // ceil(1500/32) adjacency bitmask words per row
constexpr int ZCH  = 6;           // attention j-splits (R11 proven config)
constexpr int JRANGE = 256;       // j per split
constexpr int TI   = 128;         // attention i-tile (4 rows per thread)

#define DEVINL __device__ __forceinline__
typedef unsigned long long ull;

// ---------------- scratch (device globals; no allocation allowed) ----------
__device__ __align__(16) float d_Wp0[64 * 256];    // [j][u][gate] packed, layer0 Whh
__device__ __align__(16) float d_Wp1i[64 * 256];   // layer1 Wih packed
__device__ __align__(16) float d_Wp1h[64 * 256];   // layer1 Whh packed
__device__ float d_b0[256], d_b1[256];
__device__ __align__(16) float d_g0WT[64 * 64], d_g1WT[64 * 64];
__device__ __align__(16) float d_h [BN * 64];      // LSTM out
__device__ __align__(16) float d_h2[BN * 64];      // GAT0 out
__device__ __align__(16) float d_hp[BN * 64];      // projected features (per layer)
__device__ __align__(16) float4 d_esv[BN * 4];     // (exp(es), exp(0.2es), es, 0)
__device__ __align__(16) float4 d_edv[BN * 4];     // (exp(ed), exp(0.2ed), ed, 0)
__device__ unsigned d_adjb[Nn * NW];               // bitpacked adjacency
__device__ __align__(16) float d_pacc[ZCH * BN * 64];
__device__ float d_pss[ZCH * BN * 4];

// HW tanh (MUFU.TANH): 1 MUFU vs exp+add+rcp chain. Re-landed ALONE this round.
DEVINL float ftanh(float z) {
    float r;
    asm("tanh.approx.f32 %0, %1;" : "=f"(r) : "f"(z));
    return r;
}
DEVINL float fsig(float z)  { return fmaf(ftanh(0.5f * z), 0.5f, 0.5f); }

// ---- packed fp32x2 helpers -------------------------------------------------
DEVINL ull dup2(float x) {
    ull r; unsigned xi = __float_as_uint(x);
    asm("mov.b64 %0, {%1, %1};" : "=l"(r) : "r"(xi));
    return r;
}
DEVINL ull pk2(float lo, float hi) {
    ull r;
    asm("mov.b64 %0, {%1, %2};" : "=l"(r)
        : "r"(__float_as_uint(lo)), "r"(__float_as_uint(hi)));
    return r;
}
DEVINL ull ffma2(ull a, ull b, ull c) {
    ull d;
    asm("fma.rn.f32x2 %0, %1, %2, %3;" : "=l"(d) : "l"(a), "l"(b), "l"(c));
    return d;
}
DEVINL float2 unpk(ull v) {
    unsigned lo, hi;
    asm("mov.b64 {%0, %1}, %2;" : "=r"(lo), "=r"(hi) : "l"(v));
    return make_float2(__uint_as_float(lo), __uint_as_float(hi));
}

// ---------------- prep: packed transposes + fused biases + adj bitpack ------
__global__ void prep_kernel(const float* __restrict__ adj_,
                            const float* __restrict__ Whh0,
                            const float* __restrict__ bih0, const float* __restrict__ bhh0,
                            const float* __restrict__ Wih1, const float* __restrict__ Whh1,
                            const float* __restrict__ bih1, const float* __restrict__ bhh1,
                            const float* __restrict__ g0W,  const float* __restrict__ g1W)
{
    const int* __restrict__ adj = (const int*)adj_;
    int idx = blockIdx.x * blockDim.x + threadIdx.x;
    if (idx < 16384) {
        int r = idx >> 6, j = idx & 63;
        int g = r >> 6, u = r & 63;
        int p = j * 256 + u * 4 + g;
        d_Wp0 [p] = Whh0[idx];
        d_Wp1i[p] = Wih1[idx];
        d_Wp1h[p] = Whh1[idx];
    }
    if (idx < 256) {
        d_b0[idx] = bih0[idx] + bhh0[idx];
        d_b1[idx] = bih1[idx] + bhh1[idx];
    }
    if (idx < 4096) {
        int o = idx >> 6, k = idx & 63;
        d_g0WT[k * 64 + o] = g0W[idx];
        d_g1WT[k * 64 + o] = g1W[idx];
    }
    if (idx < Nn * NW) {
        int i = idx / NW, w = idx % NW;
        unsigned m = 0;
        int jb = w * 32;
#pragma unroll 8
        for (int b = 0; b < 32; ++b) {
            int j = jb + b;
            if (j < Nn && adj[i * Nn + j] > 0) m |= (1u << b);
        }
        d_adjb[idx] = m;
    }
}

// ---------------- 2-layer LSTM (fp32x2, float4 weights + reg-dup) -----------
__global__ __launch_bounds__(256) void lstm_kernel(
    const float* __restrict__ x, const float* __restrict__ Wih0)
{
    __shared__ __align__(16) float xs[Tt][SPB];
    __shared__ __align__(16) float h0s[2][HID_][SPBP];
    __shared__ __align__(16) float h1s[2][HID_][SPBP];

    const int tid = threadIdx.x;
    const int u   = tid & 63;
    const int sg  = tid >> 6;
    const int sbase = sg * 8;
    const int bn0 = blockIdx.x * SPB;

    for (int idx = tid; idx < Tt * SPB; idx += 256) {
        int tt = idx / SPB, s = idx % SPB;
        int bn = bn0 + s;
        int b = bn / Nn, n = bn % Nn;
        xs[tt][s] = x[(b * Tt + tt) * Nn + n];
    }
    for (int idx = tid; idx < HID_ * SPBP; idx += 256) {
        (&h0s[0][0][0])[idx] = 0.f;
        (&h1s[0][0][0])[idx] = 0.f;
    }

    float c0[8], c1[8];
#pragma unroll
    for (int s = 0; s < 8; ++s) { c0[s] = 0.f; c1[s] = 0.f; }

    const ull wi0_i2 = dup2(Wih0[u]),       wi0_f2 = dup2(Wih0[64 + u]);
    const ull wi0_g2 = dup2(Wih0[128 + u]), wi0_o2 = dup2(Wih0[192 + u]);
    const ull b0_i2 = dup2(d_b0[u]), b0_f2 = dup2(d_b0[64 + u]);
    const ull b0_g2 = dup2(d_b0[128 + u]), b0_o2 = dup2(d_b0[192 + u]);
    const ull b1_i2 = dup2(d_b1[u]), b1_f2 = dup2(d_b1[64 + u]);
    const ull b1_g2 = dup2(d_b1[128 + u]), b1_o2 = dup2(d_b1[192 + u]);

    const float4* __restrict__ Wp0  = (const float4*)&d_Wp0 [u * 4];
    const float4* __restrict__ Wp1i = (const float4*)&d_Wp1i[u * 4];
    const float4* __restrict__ Wp1h = (const float4*)&d_Wp1h[u * 4];

    __syncthreads();

    float h1v[8];
    for (int t = 0; t < Tt; ++t) {
        const int cur = t & 1, nxt = cur ^ 1;
        ull ai2[4], af2[4], ag2[4], ao2[4];
        // ---- layer 0 init from x ----
        {
            ulonglong2 xA = *(const ulonglong2*)&xs[t][sbase];
            ulonglong2 xB = *(const ulonglong2*)&xs[t][sbase + 4];
            ull xv2[4] = {xA.x, xA.y, xB.x, xB.y};
#pragma unroll
            for (int p = 0; p < 4; ++p) {
                ai2[p] = ffma2(wi0_i2, xv2[p], b0_i2);
                af2[p] = ffma2(wi0_f2, xv2[p], b0_f2);
                ag2[p] = ffma2(wi0_g2, xv2[p], b0_g2);
                ao2[p] = ffma2(wi0_o2, xv2[p], b0_o2);
            }
        }
#pragma unroll 4
        for (int j = 0; j < HID_; ++j) {
            float4 w = Wp0[j * 64];
            ull wx = dup2(w.x), wy = dup2(w.y), wz = dup2(w.z), ww = dup2(w.w);
            ulonglong2 hA = *(const ulonglong2*)&h0s[cur][j][sbase];
            ulonglong2 hB = *(const ulonglong2*)&h0s[cur][j][sbase + 4];
            ull hv2[4] = {hA.x, hA.y, hB.x, hB.y};
#pragma unroll
            for (int p = 0; p < 4; ++p) {
                ai2[p] = ffma2(wx, hv2[p], ai2[p]);
                af2[p] = ffma2(wy, hv2[p], af2[p]);
                ag2[p] = ffma2(wz, hv2[p], ag2[p]);
                ao2[p] = ffma2(ww, hv2[p], ao2[p]);
            }
        }
        float h0v[8];
#pragma unroll
        for (int p = 0; p < 4; ++p) {
            float2 vi = unpk(ai2[p]), vf = unpk(af2[p]);
            float2 vg = unpk(ag2[p]), vo = unpk(ao2[p]);
            int s0 = 2 * p, s1 = 2 * p + 1;
            c0[s0] = fmaf(fsig(vf.x), c0[s0], fsig(vi.x) * ftanh(vg.x));
            h0v[s0] = fsig(vo.x) * ftanh(c0[s0]);
            c0[s1] = fmaf(fsig(vf.y), c0[s1], fsig(vi.y) * ftanh(vg.y));
            h0v[s1] = fsig(vo.y) * ftanh(c0[s1]);
        }
#pragma unroll
        for (int s = 0; s < 8; ++s) h0s[nxt][u][sbase + s] = h0v[s];
        __syncthreads();

        // ---- layer 1 ----
#pragma unroll
        for (int p = 0; p < 4; ++p) {
            ai2[p] = b1_i2; af2[p] = b1_f2; ag2[p] = b1_g2; ao2[p] = b1_o2;
        }
#pragma unroll 4
        for (int j = 0; j < HID_; ++j) {
            float4 w = Wp1i[j * 64];
            ull wx = dup2(w.x), wy = dup2(w.y), wz = dup2(w.z), ww = dup2(w.w);
            ulonglong2 hA = *(const ulonglong2*)&h0s[nxt][j][sbase];
            ulonglong2 hB = *(const ulonglong2*)&h0s[nxt][j][sbase + 4];
            ull hv2[4] = {hA.x, hA.y, hB.x, hB.y};
#pragma unroll
            for (int p = 0; p < 4; ++p) {
                ai2[p] = ffma2(wx, hv2[p], ai2[p]);
                af2[p] = ffma2(wy, hv2[p], af2[p]);
                ag2[p] = ffma2(wz, hv2[p], ag2[p]);
                ao2[p] = ffma2(ww, hv2[p], ao2[p]);
            }
        }
#pragma unroll 4
        for (int j = 0; j < HID_; ++j) {
            float4 w = Wp1h[j * 64];
            ull wx = dup2(w.x), wy = dup2(w.y), wz = dup2(w.z), ww = dup2(w.w);
            ulonglong2 hA = *(const ulonglong2*)&h1s[cur][j][sbase];
            ulonglong2 hB = *(const ulonglong2*)&h1s[cur][j][sbase + 4];
            ull hv2[4] = {hA.x, hA.y, hB.x, hB.y};
#pragma unroll
            for (int p = 0; p < 4; ++p) {
                ai2[p] = ffma2(wx, hv2[p], ai2[p]);
                af2[p] = ffma2(wy, hv2[p], af2[p]);
                ag2[p] = ffma2(wz, hv2[p], ag2[p]);
                ao2[p] = ffma2(ww, hv2[p], ao2[p]);
            }
        }
#pragma unroll
        for (int p = 0; p < 4; ++p) {
            float2 vi = unpk(ai2[p]), vf = unpk(af2[p]);
            float2 vg = unpk(ag2[p]), vo = unpk(ao2[p]);
            int s0 = 2 * p, s1 = 2 * p + 1;
            c1[s0] = fmaf(fsig(vf.x), c1[s0], fsig(vi.x) * ftanh(vg.x));
            h1v[s0] = fsig(vo.x) * ftanh(c1[s0]);
            c1[s1] = fmaf(fsig(vf.y), c1[s1], fsig(vi.y) * ftanh(vg.y));
            h1v[s1] = fsig(vo.y) * ftanh(c1[s1]);
        }
#pragma unroll
        for (int s = 0; s < 8; ++s) h1s[nxt][u][sbase + s] = h1v[s];
        __syncthreads();
    }

#pragma unroll
    for (int s = 0; s < 8; ++s)
        d_h[(bn0 + sbase + s) * 64 + u] = h1v[s];
}

// ---------------- GAT projection + factorized attention exponentials -------
template <int LAYER>
__global__ __launch_bounds__(256) void gat_proj_kernel(
    const float* __restrict__ asrc, const float* __restrict__ adst)
{
    const float* __restrict__ hin = (LAYER == 0) ? d_h : d_h2;
    const float* __restrict__ WT  = (LAYER == 0) ? d_g0WT : d_g1WT;

    const int t  = threadIdx.x;
    const int o  = t & 63;
    const int lo = t >> 6;
    const int bn = blockIdx.x * 4 + lo;

    __shared__ float hs[4][64];
    hs[lo][o] = hin[bn * 64 + o];
    __syncthreads();

    float acc = 0.f;
#pragma unroll
    for (int k = 0; k < 64; ++k)
        acc = fmaf(hs[lo][k], WT[k * 64 + o], acc);

    d_hp[bn * 64 + o] = acc;

    float vs = acc * asrc[o];
    float vd = acc * adst[o];
#pragma unroll
    for (int off = 8; off > 0; off >>= 1) {
        vs += __shfl_down_sync(0xffffffffu, vs, off, 16);
        vd += __shfl_down_sync(0xffffffffu, vd, off, 16);
    }
    if ((o & 15) == 0) {
        int hh = o >> 4;
        d_esv[bn * 4 + hh] = make_float4(__expf(vs), __expf(0.2f * vs), vs, 0.f);
        d_edv[bn * 4 + hh] = make_float4(__expf(vd), __expf(0.2f * vd), vd, 0.f);
    }
}

// ---------------- GAT attention aggregate (6-way j-split, 4 rows/thread) ----
// block: 128 threads = 32 rslots x 4 heads; each thread owns 4 rows
// grid: (ceil(N/128), B, ZCH) = 576 blocks (R11 proven config)
__global__ __launch_bounds__(128) void gat_attn_kernel()
{
    constexpr int JC = 64;
    const int b  = blockIdx.y;
    const int z  = blockIdx.z;
    const int i0 = blockIdx.x * TI;
    const int t  = threadIdx.x;
    const int h  = t & 3;
    const int rs = t >> 2;

    float* __restrict__ pacc = d_pacc + z * (BN * 64);
    float* __restrict__ pss  = d_pss  + z * (BN * 4);

    __shared__ __align__(16) float4 hps4[JC][4][5];  // 20 KB, padded per head
    __shared__ __align__(16) float4 edvs[JC][4];     // 4 KB
    __shared__ unsigned adjw[TI][2];                 // 1 KB

    ull acc2[4][8];
#pragma unroll
    for (int r = 0; r < 4; ++r)
#pragma unroll
        for (int d = 0; d < 8; ++d) acc2[r][d] = 0ull;
    ull ssum01 = 0ull, ssum23 = 0ull;
    const ull one2 = dup2(1.f);

    int   irow[4];
    float esA[4], esB[4], esr[4];
#pragma unroll
    for (int r = 0; r < 4; ++r) {
        irow[r] = i0 + rs + 32 * r;
        float4 ev = make_float4(0.f, 0.f, 0.f, 0.f);
        if (irow[r] < Nn) ev = d_esv[(b * Nn + irow[r]) * 4 + h];
        esA[r] = ev.x; esB[r] = ev.y; esr[r] = ev.z;
    }

    const int jbeg = z * JRANGE;
    const int jend = min(jbeg + JRANGE, Nn);

    for (int j0 = jbeg; j0 < jend; j0 += JC) {
        __syncthreads();
        for (int idx = t; idx < JC * 16; idx += 128) {
            int jj = idx >> 4, k4 = idx & 15;
            int j = j0 + jj;
            float4 v = make_float4(0.f, 0.f, 0.f, 0.f);
            if (j < Nn) v = ((const float4*)d_hp)[(b * Nn + j) * 16 + k4];
            hps4[jj][k4 >> 2][k4 & 3] = v;
        }
        for (int idx = t; idx < JC * 4; idx += 128) {
            int jj = idx >> 2, hh = idx & 3;
            int j = j0 + jj;
            float4 v = make_float4(0.f, 0.f, 0.f, 0.f);
            if (j < Nn) v = d_edv[(b * Nn + j) * 4 + hh];
            edvs[jj][hh] = v;
        }
        {
            int i = i0 + t;
            int w0 = j0 >> 5;
#pragma unroll
            for (int w = 0; w < 2; ++w) {
                unsigned m = 0;
                if (i < Nn && (w0 + w) < NW) m = d_adjb[i * NW + w0 + w];
                adjw[t][w] = m;
            }
        }
        __syncthreads();

#pragma unroll
        for (int w = 0; w < 2; ++w) {
            unsigned m0 = adjw[rs][w];
            unsigned m1 = adjw[rs + 32][w];
            unsigned m2 = adjw[rs + 64][w];
            unsigned m3 = adjw[rs + 96][w];
            const int jjb = w * 32;
#pragma unroll 2
            for (int bp = 0; bp < 32; ++bp) {
                const int jj = jjb + bp;
                float4 ed = edvs[jj][h];
                const ulonglong2* q = (const ulonglong2*)&hps4[jj][h][0];
                ulonglong2 qa = q[0], qb = q[1];

                float p[4];
                {
                    float e0 = esr[0] + ed.z;
                    float s0 = ((e0 > 0.f) ? esA[0] : esB[0]) * ((e0 > 0.f) ? ed.x : ed.y);
                    p[0] = (m0 & (1u << bp)) ? s0 : 0.f;
                    float e1 = esr[1] + ed.z;
                    float s1 = ((e1 > 0.f) ? esA[1] : esB[1]) * ((e1 > 0.f) ? ed.x : ed.y);
                    p[1] = (m1 & (1u << bp)) ? s1 : 0.f;
                    float e2 = esr[2] + ed.z;
                    float s2 = ((e2 > 0.f) ? esA[2] : esB[2]) * ((e2 > 0.f) ? ed.x : ed.y);
                    p[2] = (m2 & (1u << bp)) ? s2 : 0.f;
                    float e3 = esr[3] + ed.z;
                    float s3 = ((e3 > 0.f) ? esA[3] : esB[3]) * ((e3 > 0.f) ? ed.x : ed.y);
                    p[3] = (m3 & (1u << bp)) ? s3 : 0.f;
                }
                ssum01 = ffma2(pk2(p[0], p[1]), one2, ssum01);
                ssum23 = ffma2(pk2(p[2], p[3]), one2, ssum23);

                ull pp[4] = {dup2(p[0]), dup2(p[1]), dup2(p[2]), dup2(p[3])};
#pragma unroll
                for (int r = 0; r < 4; ++r) {
                    acc2[r][0] = ffma2(pp[r], qa.x, acc2[r][0]);
                    acc2[r][1] = ffma2(pp[r], qa.y, acc2[r][1]);
                    acc2[r][2] = ffma2(pp[r], qb.x, acc2[r][2]);
                    acc2[r][3] = ffma2(pp[r], qb.y, acc2[r][3]);
                }
                ulonglong2 qc = *(const ulonglong2*)&hps4[jj][h][2];
                ulonglong2 qd = *(const ulonglong2*)&hps4[jj][h][3];
#pragma unroll
                for (int r = 0; r < 4; ++r) {
                    acc2[r][4] = ffma2(pp[r], qc.x, acc2[r][4]);
                    acc2[r][5] = ffma2(pp[r], qc.y, acc2[r][5]);
                    acc2[r][6] = ffma2(pp[r], qd.x, acc2[r][6]);
                    acc2[r][7] = ffma2(pp[r], qd.y, acc2[r][7]);
                }
            }
        }
    }

    float2 s01 = unpk(ssum01), s23 = unpk(ssum23);
    float ssum[4] = {s01.x, s01.y, s23.x, s23.y};
#pragma unroll
    for (int r = 0; r < 4; ++r) {
        if (irow[r] < Nn) {
            int bn = b * Nn + irow[r];
            pss[bn * 4 + h] = ssum[r];
            ulonglong2* dst = (ulonglong2*)&pacc[bn * 64 + h * 16];
#pragma unroll
            for (int k = 0; k < 4; ++k)
                dst[k] = make_ulonglong2(acc2[r][2 * k], acc2[r][2 * k + 1]);
        }
    }
}

// ---------------- layer-0 combine: normalize + ReLU -> d_h2 -----------------
__global__ __launch_bounds__(256) void gat_combine_kernel()
{
    int idx = blockIdx.x * 256 + threadIdx.x;      // over BN*16 float4s
    if (idx >= BN * 16) return;
    int bn = idx >> 4;
    int f4 = idx & 15;
    int h  = f4 >> 2;
    float s = 0.f;
#pragma unroll
    for (int z = 0; z < ZCH; ++z) s += d_pss[z * (BN * 4) + bn * 4 + h];
    float inv = (s > 0.f) ? __fdividef(1.f, s) : 0.f;
    float4 a = make_float4(0.f, 0.f, 0.f, 0.f);
#pragma unroll
    for (int z = 0; z < ZCH; ++z) {
        float4 v = ((const float4*)(d_pacc + z * (BN * 64)))[idx];
        a.x += v.x; a.y += v.y; a.z += v.z; a.w += v.w;
    }
    float4 v;
    v.x = fmaxf(a.x * inv, 0.f);
    v.y = fmaxf(a.y * inv, 0.f);
    v.z = fmaxf(a.z * inv, 0.f);
    v.w = fmaxf(a.w * inv, 0.f);
    ((float4*)d_h2)[idx] = v;
}

// ---------------- layer-1 combine fused with output head --------------------
// 16 consecutive threads own one node's 64 feats (f4 = idx & 15) -> half-warp
// width-16 shfl reduction for the 3 output dots; no d_h round trip.
__global__ __launch_bounds__(256) void gat_combine_out_kernel(
    const float* __restrict__ outW, const float* __restrict__ outb,
    float* __restrict__ out)
{
    int idx = blockIdx.x * 256 + threadIdx.x;      // over BN*16 float4s
    if (idx >= BN * 16) return;
    int bn = idx >> 4;
    int f4 = idx & 15;
    int h  = f4 >> 2;
    float s = 0.f;
#pragma unroll
    for (int z = 0; z < ZCH; ++z) s += d_pss[z * (BN * 4) + bn * 4 + h];
    float inv = (s > 0.f) ? __fdividef(1.f, s) : 0.f;
    float4 a = make_float4(0.f, 0.f, 0.f, 0.f);
#pragma unroll
    for (int z = 0; z < ZCH; ++z) {
        float4 v = ((const float4*)(d_pacc + z * (BN * 64)))[idx];
        a.x += v.x; a.y += v.y; a.z += v.z; a.w += v.w;
    }
    float4 v;
    v.x = fmaxf(a.x * inv, 0.f);
    v.y = fmaxf(a.y * inv, 0.f);
    v.z = fmaxf(a.z * inv, 0.f);
    v.w = fmaxf(a.w * inv, 0.f);

    // output head: p[o] = sum_k h[k]*outW[o*64+k], reduced over the 16 lanes
    const int base = f4 * 4;
    float p0, p1, p2;
    {
        const float4 w0 = *(const float4*)&outW[0 * 64 + base];
        const float4 w1 = *(const float4*)&outW[1 * 64 + base];
        const float4 w2 = *(const float4*)&outW[2 * 64 + base];
        p0 = v.x * w0.x + v.y * w0.y + v.z * w0.z + v.w * w0.w;
        p1 = v.x * w1.x + v.y * w1.y + v.z * w1.z + v.w * w1.w;
        p2 = v.x * w2.x + v.y * w2.y + v.z * w2.z + v.w * w2.w;
    }
#pragma unroll
    for (int off = 8; off > 0; off >>= 1) {
        p0 += __shfl_down_sync(0xffffffffu, p0, off, 16);
        p1 += __shfl_down_sync(0xffffffffu, p1, off, 16);
        p2 += __shfl_down_sync(0xffffffffu, p2, off, 16);
    }
    if (f4 == 0) {
        int b = bn / Nn, n = bn % Nn;
        out[b * 3 * Nn + 0 * Nn + n] = p0 + outb[0];
        out[b * 3 * Nn + 1 * Nn + n] = p1 + outb[1];
        out[b * 3 * Nn + 2 * Nn + n] = p2 + outb[2];
    }
}

// ---------------- launch ----------------------------------------------------
extern "C" void kernel_launch(void* const* d_in, const int* in_sizes, int n_in,
                              void* d_out, int out_size)
{
    const float* x     = (const float*)d_in[0];
    const float* adj   = (const float*)d_in[1];   // int32 payload, cast inside prep
    const float* Wih0  = (const float*)d_in[2];
    const float* Whh0  = (const float*)d_in[3];
    const float* bih0  = (const float*)d_in[4];
    const float* bhh0  = (const float*)d_in[5];
    const float* Wih1  = (const float*)d_in[6];
    const float* Whh1  = (const float*)d_in[7];
    const float* bih1  = (const float*)d_in[8];
    const float* bhh1  = (const float*)d_in[9];
    const float* g0W   = (const float*)d_in[10];
    const float* g0as  = (const float*)d_in[11];
    const float* g0ad  = (const float*)d_in[12];
    const float* g1W   = (const float*)d_in[13];
    const float* g1as  = (const float*)d_in[14];
    const float* g1ad  = (const float*)d_in[15];
    const float* outW  = (const float*)d_in[16];
    const float* outb  = (const float*)d_in[17];
    float* out = (float*)d_out;

    prep_kernel<<<(Nn * NW + 255) / 256, 256>>>(adj, Whh0, bih0, bhh0,
                                                Wih1, Whh1, bih1, bhh1, g0W, g1W);
    lstm_kernel<<<BN / SPB, 256>>>(x, Wih0);

    dim3 agrid((Nn + TI - 1) / TI, Bb, ZCH);

    gat_proj_kernel<0><<<BN / 4, 256>>>(g0as, g0ad);
    gat_attn_kernel<<<agrid, 128>>>();
    gat_combine_kernel<<<(BN * 16 + 255) / 256, 256>>>();

    gat_proj_kernel<1><<<BN / 4, 256>>>(g1as, g1ad);
    gat_attn_kernel<<<agrid, 128>>>();
    gat_combine_out_kernel<<<(BN * 16 + 255) / 256, 256>>>(outW, outb, out);
}

// round 15
// speedup vs baseline: 1.8311x; 1.1316x over previous
#include <cuda_runtime.h>

// Problem constants (fixed shapes from reference)
constexpr int Bb   = 8;
constexpr int Tt   = 12;
constexpr int Nn   = 1500;
constexpr int HID_ = 64;
constexpr int BN   = Bb * Nn;     // 12000
constexpr int SPB  = 16;          // sequences per LSTM block (small blocks)
constexpr int SPBP = 20;          // padded row (16+4)
constexpr int NW   = 47;          // ceil(1500/32) adjacency bitmask words per row
constexpr int ZCH  = 6;           // attention j-splits (proven config)
constexpr int JRANGE = 256;       // j per split
constexpr int TI   = 128;         // attention i-tile (4 rows per thread)

#define DEVINL __device__ __forceinline__
typedef unsigned long long ull;

// ---------------- scratch (device globals; no allocation allowed) ----------
__device__ __align__(16) float d_Wp0[64 * 256];    // [j][u][gate] packed, layer0 Whh
__device__ __align__(16) float d_Wp1i[64 * 256];   // layer1 Wih packed
__device__ __align__(16) float d_Wp1h[64 * 256];   // layer1 Whh packed
__device__ float d_b0[256], d_b1[256];
__device__ __align__(16) float d_g0WT[64 * 64], d_g1WT[64 * 64];
__device__ __align__(16) float d_h [BN * 64];      // LSTM out
__device__ __align__(16) float d_h2[BN * 64];      // GAT0 out
__device__ __align__(16) float d_hp[BN * 64];      // projected features (per layer)
__device__ __align__(16) float4 d_esv[BN * 4];     // (exp(es), exp(0.2es), es, 0)
__device__ __align__(16) float4 d_edv[BN * 4];     // (exp(ed), exp(0.2ed), ed, 0)
__device__ unsigned d_adjb[Nn * NW];               // bitpacked adjacency
__device__ __align__(16) float d_pacc[ZCH * BN * 64];
__device__ float d_pss[ZCH * BN * 4];

// HW tanh (MUFU.TANH)
DEVINL float ftanh(float z) {
    float r;
    asm("tanh.approx.f32 %0, %1;" : "=f"(r) : "f"(z));
    return r;
}
DEVINL float fsig(float z)  { return fmaf(ftanh(0.5f * z), 0.5f, 0.5f); }

// ---- packed fp32x2 helpers -------------------------------------------------
DEVINL ull dup2(float x) {
    ull r; unsigned xi = __float_as_uint(x);
    asm("mov.b64 %0, {%1, %1};" : "=l"(r) : "r"(xi));
    return r;
}
DEVINL ull pk2(float lo, float hi) {
    ull r;
    asm("mov.b64 %0, {%1, %2};" : "=l"(r)
        : "r"(__float_as_uint(lo)), "r"(__float_as_uint(hi)));
    return r;
}
DEVINL ull ffma2(ull a, ull b, ull c) {
    ull d;
    asm("fma.rn.f32x2 %0, %1, %2, %3;" : "=l"(d) : "l"(a), "l"(b), "l"(c));
    return d;
}
DEVINL float2 unpk(ull v) {
    unsigned lo, hi;
    asm("mov.b64 {%0, %1}, %2;" : "=r"(lo), "=r"(hi) : "l"(v));
    return make_float2(__uint_as_float(lo), __uint_as_float(hi));
}

// ---------------- prep: packed transposes + fused biases + adj bitpack ------
__global__ void prep_kernel(const float* __restrict__ adj_,
                            const float* __restrict__ Whh0,
                            const float* __restrict__ bih0, const float* __restrict__ bhh0,
                            const float* __restrict__ Wih1, const float* __restrict__ Whh1,
                            const float* __restrict__ bih1, const float* __restrict__ bhh1,
                            const float* __restrict__ g0W,  const float* __restrict__ g1W)
{
    const int* __restrict__ adj = (const int*)adj_;
    int idx = blockIdx.x * blockDim.x + threadIdx.x;
    if (idx < 16384) {
        int r = idx >> 6, j = idx & 63;
        int g = r >> 6, u = r & 63;
        int p = j * 256 + u * 4 + g;
        d_Wp0 [p] = Whh0[idx];
        d_Wp1i[p] = Wih1[idx];
        d_Wp1h[p] = Whh1[idx];
    }
    if (idx < 256) {
        d_b0[idx] = bih0[idx] + bhh0[idx];
        d_b1[idx] = bih1[idx] + bhh1[idx];
    }
    if (idx < 4096) {
        int o = idx >> 6, k = idx & 63;
        d_g0WT[k * 64 + o] = g0W[idx];
        d_g1WT[k * 64 + o] = g1W[idx];
    }
    if (idx < Nn * NW) {
        int i = idx / NW, w = idx % NW;
        unsigned m = 0;
        int jb = w * 32;
#pragma unroll 8
        for (int b = 0; b < 32; ++b) {
            int j = jb + b;
            if (j < Nn && adj[i * Nn + j] > 0) m |= (1u << b);
        }
        d_adjb[idx] = m;
    }
}

// ---------------- 2-layer LSTM: 128-thread blocks, 5 CTAs/SM ----------------
// 16 seqs/block = 2 groups x 8 seqs/thread (per-thread inner loop unchanged)
__global__ __launch_bounds__(128, 5) void lstm_kernel(
    const float* __restrict__ x, const float* __restrict__ Wih0)
{
    __shared__ __align__(16) float xs[Tt][SPB];
    __shared__ __align__(16) float h0s[2][HID_][SPBP];
    __shared__ __align__(16) float h1s[2][HID_][SPBP];

    const int tid = threadIdx.x;
    const int u   = tid & 63;
    const int sg  = tid >> 6;          // 0..1
    const int sbase = sg * 8;
    const int bn0 = blockIdx.x * SPB;

    for (int idx = tid; idx < Tt * SPB; idx += 128) {
        int tt = idx / SPB, s = idx % SPB;
        int bn = bn0 + s;
        int b = bn / Nn, n = bn % Nn;
        xs[tt][s] = x[(b * Tt + tt) * Nn + n];
    }
    for (int idx = tid; idx < 2 * HID_ * SPBP; idx += 128) {
        (&h0s[0][0][0])[idx] = 0.f;
        (&h1s[0][0][0])[idx] = 0.f;
    }

    float c0[8], c1[8];
#pragma unroll
    for (int s = 0; s < 8; ++s) { c0[s] = 0.f; c1[s] = 0.f; }

    const ull wi0_i2 = dup2(Wih0[u]),       wi0_f2 = dup2(Wih0[64 + u]);
    const ull wi0_g2 = dup2(Wih0[128 + u]), wi0_o2 = dup2(Wih0[192 + u]);
    const ull b0_i2 = dup2(d_b0[u]), b0_f2 = dup2(d_b0[64 + u]);
    const ull b0_g2 = dup2(d_b0[128 + u]), b0_o2 = dup2(d_b0[192 + u]);
    const ull b1_i2 = dup2(d_b1[u]), b1_f2 = dup2(d_b1[64 + u]);
    const ull b1_g2 = dup2(d_b1[128 + u]), b1_o2 = dup2(d_b1[192 + u]);

    const float4* __restrict__ Wp0  = (const float4*)&d_Wp0 [u * 4];
    const float4* __restrict__ Wp1i = (const float4*)&d_Wp1i[u * 4];
    const float4* __restrict__ Wp1h = (const float4*)&d_Wp1h[u * 4];

    __syncthreads();

    float h1v[8];
    for (int t = 0; t < Tt; ++t) {
        const int cur = t & 1, nxt = cur ^ 1;
        ull ai2[4], af2[4], ag2[4], ao2[4];
        // ---- layer 0 init from x ----
        {
            ulonglong2 xA = *(const ulonglong2*)&xs[t][sbase];
            ulonglong2 xB = *(const ulonglong2*)&xs[t][sbase + 4];
            ull xv2[4] = {xA.x, xA.y, xB.x, xB.y};
#pragma unroll
            for (int p = 0; p < 4; ++p) {
                ai2[p] = ffma2(wi0_i2, xv2[p], b0_i2);
                af2[p] = ffma2(wi0_f2, xv2[p], b0_f2);
                ag2[p] = ffma2(wi0_g2, xv2[p], b0_g2);
                ao2[p] = ffma2(wi0_o2, xv2[p], b0_o2);
            }
        }
#pragma unroll 4
        for (int j = 0; j < HID_; ++j) {
            float4 w = Wp0[j * 64];
            ull wx = dup2(w.x), wy = dup2(w.y), wz = dup2(w.z), ww = dup2(w.w);
            ulonglong2 hA = *(const ulonglong2*)&h0s[cur][j][sbase];
            ulonglong2 hB = *(const ulonglong2*)&h0s[cur][j][sbase + 4];
            ull hv2[4] = {hA.x, hA.y, hB.x, hB.y};
#pragma unroll
            for (int p = 0; p < 4; ++p) {
                ai2[p] = ffma2(wx, hv2[p], ai2[p]);
                af2[p] = ffma2(wy, hv2[p], af2[p]);
                ag2[p] = ffma2(wz, hv2[p], ag2[p]);
                ao2[p] = ffma2(ww, hv2[p], ao2[p]);
            }
        }
        float h0v[8];
#pragma unroll
        for (int p = 0; p < 4; ++p) {
            float2 vi = unpk(ai2[p]), vf = unpk(af2[p]);
            float2 vg = unpk(ag2[p]), vo = unpk(ao2[p]);
            int s0 = 2 * p, s1 = 2 * p + 1;
            c0[s0] = fmaf(fsig(vf.x), c0[s0], fsig(vi.x) * ftanh(vg.x));
            h0v[s0] = fsig(vo.x) * ftanh(c0[s0]);
            c0[s1] = fmaf(fsig(vf.y), c0[s1], fsig(vi.y) * ftanh(vg.y));
            h0v[s1] = fsig(vo.y) * ftanh(c0[s1]);
        }
#pragma unroll
        for (int s = 0; s < 8; ++s) h0s[nxt][u][sbase + s] = h0v[s];
        __syncthreads();

        // ---- layer 1 ----
#pragma unroll
        for (int p = 0; p < 4; ++p) {
            ai2[p] = b1_i2; af2[p] = b1_f2; ag2[p] = b1_g2; ao2[p] = b1_o2;
        }
#pragma unroll 4
        for (int j = 0; j < HID_; ++j) {
            float4 w = Wp1i[j * 64];
            ull wx = dup2(w.x), wy = dup2(w.y), wz = dup2(w.z), ww = dup2(w.w);
            ulonglong2 hA = *(const ulonglong2*)&h0s[nxt][j][sbase];
            ulonglong2 hB = *(const ulonglong2*)&h0s[nxt][j][sbase + 4];
            ull hv2[4] = {hA.x, hA.y, hB.x, hB.y};
#pragma unroll
            for (int p = 0; p < 4; ++p) {
                ai2[p] = ffma2(wx, hv2[p], ai2[p]);
                af2[p] = ffma2(wy, hv2[p], af2[p]);
                ag2[p] = ffma2(wz, hv2[p], ag2[p]);
                ao2[p] = ffma2(ww, hv2[p], ao2[p]);
            }
        }
#pragma unroll 4
        for (int j = 0; j < HID_; ++j) {
            float4 w = Wp1h[j * 64];
            ull wx = dup2(w.x), wy = dup2(w.y), wz = dup2(w.z), ww = dup2(w.w);
            ulonglong2 hA = *(const ulonglong2*)&h1s[cur][j][sbase];
            ulonglong2 hB = *(const ulonglong2*)&h1s[cur][j][sbase + 4];
            ull hv2[4] = {hA.x, hA.y, hB.x, hB.y};
#pragma unroll
            for (int p = 0; p < 4; ++p) {
                ai2[p] = ffma2(wx, hv2[p], ai2[p]);
                af2[p] = ffma2(wy, hv2[p], af2[p]);
                ag2[p] = ffma2(wz, hv2[p], ag2[p]);
                ao2[p] = ffma2(ww, hv2[p], ao2[p]);
            }
        }
#pragma unroll
        for (int p = 0; p < 4; ++p) {
            float2 vi = unpk(ai2[p]), vf = unpk(af2[p]);
            float2 vg = unpk(ag2[p]), vo = unpk(ao2[p]);
            int s0 = 2 * p, s1 = 2 * p + 1;
            c1[s0] = fmaf(fsig(vf.x), c1[s0], fsig(vi.x) * ftanh(vg.x));
            h1v[s0] = fsig(vo.x) * ftanh(c1[s0]);
            c1[s1] = fmaf(fsig(vf.y), c1[s1], fsig(vi.y) * ftanh(vg.y));
            h1v[s1] = fsig(vo.y) * ftanh(c1[s1]);
        }
#pragma unroll
        for (int s = 0; s < 8; ++s) h1s[nxt][u][sbase + s] = h1v[s];
        __syncthreads();
    }

#pragma unroll
    for (int s = 0; s < 8; ++s)
        d_h[(bn0 + sbase + s) * 64 + u] = h1v[s];
}

// ---------------- GAT projection + factorized attention exponentials -------
template <int LAYER>
__global__ __launch_bounds__(256) void gat_proj_kernel(
    const float* __restrict__ asrc, const float* __restrict__ adst)
{
    const float* __restrict__ hin = (LAYER == 0) ? d_h : d_h2;
    const float* __restrict__ WT  = (LAYER == 0) ? d_g0WT : d_g1WT;

    const int t  = threadIdx.x;
    const int o  = t & 63;
    const int lo = t >> 6;
    const int bn = blockIdx.x * 4 + lo;

    __shared__ float hs[4][64];
    hs[lo][o] = hin[bn * 64 + o];
    __syncthreads();

    float acc = 0.f;
#pragma unroll
    for (int k = 0; k < 64; ++k)
        acc = fmaf(hs[lo][k], WT[k * 64 + o], acc);

    d_hp[bn * 64 + o] = acc;

    float vs = acc * asrc[o];
    float vd = acc * adst[o];
#pragma unroll
    for (int off = 8; off > 0; off >>= 1) {
        vs += __shfl_down_sync(0xffffffffu, vs, off, 16);
        vd += __shfl_down_sync(0xffffffffu, vd, off, 16);
    }
    if ((o & 15) == 0) {
        int hh = o >> 4;
        d_esv[bn * 4 + hh] = make_float4(__expf(vs), __expf(0.2f * vs), vs, 0.f);
        d_edv[bn * 4 + hh] = make_float4(__expf(vd), __expf(0.2f * vd), vd, 0.f);
    }
}

// ---------------- GAT attention aggregate (6-way j-split, 4 rows/thread) ----
__global__ __launch_bounds__(128) void gat_attn_kernel()
{
    constexpr int JC = 64;
    const int b  = blockIdx.y;
    const int z  = blockIdx.z;
    const int i0 = blockIdx.x * TI;
    const int t  = threadIdx.x;
    const int h  = t & 3;
    const int rs = t >> 2;

    float* __restrict__ pacc = d_pacc + z * (BN * 64);
    float* __restrict__ pss  = d_pss  + z * (BN * 4);

    __shared__ __align__(16) float4 hps4[JC][4][5];  // 20 KB, padded per head
    __shared__ __align__(16) float4 edvs[JC][4];     // 4 KB
    __shared__ unsigned adjw[TI][2];                 // 1 KB

    ull acc2[4][8];
#pragma unroll
    for (int r = 0; r < 4; ++r)
#pragma unroll
        for (int d = 0; d < 8; ++d) acc2[r][d] = 0ull;
    ull ssum01 = 0ull, ssum23 = 0ull;
    const ull one2 = dup2(1.f);

    int   irow[4];
    float esA[4], esB[4], esr[4];
#pragma unroll
    for (int r = 0; r < 4; ++r) {
        irow[r] = i0 + rs + 32 * r;
        float4 ev = make_float4(0.f, 0.f, 0.f, 0.f);
        if (irow[r] < Nn) ev = d_esv[(b * Nn + irow[r]) * 4 + h];
        esA[r] = ev.x; esB[r] = ev.y; esr[r] = ev.z;
    }

    const int jbeg = z * JRANGE;
    const int jend = min(jbeg + JRANGE, Nn);

    for (int j0 = jbeg; j0 < jend; j0 += JC) {
        __syncthreads();
        for (int idx = t; idx < JC * 16; idx += 128) {
            int jj = idx >> 4, k4 = idx & 15;
            int j = j0 + jj;
            float4 v = make_float4(0.f, 0.f, 0.f, 0.f);
            if (j < Nn) v = ((const float4*)d_hp)[(b * Nn + j) * 16 + k4];
            hps4[jj][k4 >> 2][k4 & 3] = v;
        }
        for (int idx = t; idx < JC * 4; idx += 128) {
            int jj = idx >> 2, hh = idx & 3;
            int j = j0 + jj;
            float4 v = make_float4(0.f, 0.f, 0.f, 0.f);
            if (j < Nn) v = d_edv[(b * Nn + j) * 4 + hh];
            edvs[jj][hh] = v;
        }
        {
            int i = i0 + t;
            int w0 = j0 >> 5;
#pragma unroll
            for (int w = 0; w < 2; ++w) {
                unsigned m = 0;
                if (i < Nn && (w0 + w) < NW) m = d_adjb[i * NW + w0 + w];
                adjw[t][w] = m;
            }
        }
        __syncthreads();

#pragma unroll
        for (int w = 0; w < 2; ++w) {
            unsigned m0 = adjw[rs][w];
            unsigned m1 = adjw[rs + 32][w];
            unsigned m2 = adjw[rs + 64][w];
            unsigned m3 = adjw[rs + 96][w];
            const int jjb = w * 32;
#pragma unroll 2
            for (int bp = 0; bp < 32; ++bp) {
                const int jj = jjb + bp;
                float4 ed = edvs[jj][h];
                const ulonglong2* q = (const ulonglong2*)&hps4[jj][h][0];
                ulonglong2 qa = q[0], qb = q[1];

                float p[4];
                {
                    float e0 = esr[0] + ed.z;
                    float s0 = ((e0 > 0.f) ? esA[0] : esB[0]) * ((e0 > 0.f) ? ed.x : ed.y);
                    p[0] = (m0 & (1u << bp)) ? s0 : 0.f;
                    float e1 = esr[1] + ed.z;
                    float s1 = ((e1 > 0.f) ? esA[1] : esB[1]) * ((e1 > 0.f) ? ed.x : ed.y);
                    p[1] = (m1 & (1u << bp)) ? s1 : 0.f;
                    float e2 = esr[2] + ed.z;
                    float s2 = ((e2 > 0.f) ? esA[2] : esB[2]) * ((e2 > 0.f) ? ed.x : ed.y);
                    p[2] = (m2 & (1u << bp)) ? s2 : 0.f;
                    float e3 = esr[3] + ed.z;
                    float s3 = ((e3 > 0.f) ? esA[3] : esB[3]) * ((e3 > 0.f) ? ed.x : ed.y);
                    p[3] = (m3 & (1u << bp)) ? s3 : 0.f;
                }
                ssum01 = ffma2(pk2(p[0], p[1]), one2, ssum01);
                ssum23 = ffma2(pk2(p[2], p[3]), one2, ssum23);

                ull pp[4] = {dup2(p[0]), dup2(p[1]), dup2(p[2]), dup2(p[3])};
#pragma unroll
                for (int r = 0; r < 4; ++r) {
                    acc2[r][0] = ffma2(pp[r], qa.x, acc2[r][0]);
                    acc2[r][1] = ffma2(pp[r], qa.y, acc2[r][1]);
                    acc2[r][2] = ffma2(pp[r], qb.x, acc2[r][2]);
                    acc2[r][3] = ffma2(pp[r], qb.y, acc2[r][3]);
                }
                ulonglong2 qc = *(const ulonglong2*)&hps4[jj][h][2];
                ulonglong2 qd = *(const ulonglong2*)&hps4[jj][h][3];
#pragma unroll
                for (int r = 0; r < 4; ++r) {
                    acc2[r][4] = ffma2(pp[r], qc.x, acc2[r][4]);
                    acc2[r][5] = ffma2(pp[r], qc.y, acc2[r][5]);
                    acc2[r][6] = ffma2(pp[r], qd.x, acc2[r][6]);
                    acc2[r][7] = ffma2(pp[r], qd.y, acc2[r][7]);
                }
            }
        }
    }

    float2 s01 = unpk(ssum01), s23 = unpk(ssum23);
    float ssum[4] = {s01.x, s01.y, s23.x, s23.y};
#pragma unroll
    for (int r = 0; r < 4; ++r) {
        if (irow[r] < Nn) {
            int bn = b * Nn + irow[r];
            pss[bn * 4 + h] = ssum[r];
            ulonglong2* dst = (ulonglong2*)&pacc[bn * 64 + h * 16];
#pragma unroll
            for (int k = 0; k < 4; ++k)
                dst[k] = make_ulonglong2(acc2[r][2 * k], acc2[r][2 * k + 1]);
        }
    }
}

// ---------------- layer-0 combine: normalize + ReLU -> d_h2 -----------------
__global__ __launch_bounds__(256) void gat_combine_kernel()
{
    int idx = blockIdx.x * 256 + threadIdx.x;      // over BN*16 float4s
    if (idx >= BN * 16) return;
    int bn = idx >> 4;
    int f4 = idx & 15;
    int h  = f4 >> 2;
    float s = 0.f;
#pragma unroll
    for (int z = 0; z < ZCH; ++z) s += d_pss[z * (BN * 4) + bn * 4 + h];
    float inv = (s > 0.f) ? __fdividef(1.f, s) : 0.f;
    float4 a = make_float4(0.f, 0.f, 0.f, 0.f);
#pragma unroll
    for (int z = 0; z < ZCH; ++z) {
        float4 v = ((const float4*)(d_pacc + z * (BN * 64)))[idx];
        a.x += v.x; a.y += v.y; a.z += v.z; a.w += v.w;
    }
    float4 v;
    v.x = fmaxf(a.x * inv, 0.f);
    v.y = fmaxf(a.y * inv, 0.f);
    v.z = fmaxf(a.z * inv, 0.f);
    v.w = fmaxf(a.w * inv, 0.f);
    ((float4*)d_h2)[idx] = v;
}

// ---------------- layer-1 combine fused with output head --------------------
__global__ __launch_bounds__(256) void gat_combine_out_kernel(
    const float* __restrict__ outW, const float* __restrict__ outb,
    float* __restrict__ out)
{
    int idx = blockIdx.x * 256 + threadIdx.x;      // over BN*16 float4s
    if (idx >= BN * 16) return;
    int bn = idx >> 4;
    int f4 = idx & 15;
    int h  = f4 >> 2;
    float s = 0.f;
#pragma unroll
    for (int z = 0; z < ZCH; ++z) s += d_pss[z * (BN * 4) + bn * 4 + h];
    float inv = (s > 0.f) ? __fdividef(1.f, s) : 0.f;
    float4 a = make_float4(0.f, 0.f, 0.f, 0.f);
#pragma unroll
    for (int z = 0; z < ZCH; ++z) {
        float4 v = ((const float4*)(d_pacc + z * (BN * 64)))[idx];
        a.x += v.x; a.y += v.y; a.z += v.z; a.w += v.w;
    }
    float4 v;
    v.x = fmaxf(a.x * inv, 0.f);
    v.y = fmaxf(a.y * inv, 0.f);
    v.z = fmaxf(a.z * inv, 0.f);
    v.w = fmaxf(a.w * inv, 0.f);

    const int base = f4 * 4;
    float p0, p1, p2;
    {
        const float4 w0 = *(const float4*)&outW[0 * 64 + base];
        const float4 w1 = *(const float4*)&outW[1 * 64 + base];
        const float4 w2 = *(const float4*)&outW[2 * 64 + base];
        p0 = v.x * w0.x + v.y * w0.y + v.z * w0.z + v.w * w0.w;
        p1 = v.x * w1.x + v.y * w1.y + v.z * w1.z + v.w * w1.w;
        p2 = v.x * w2.x + v.y * w2.y + v.z * w2.z + v.w * w2.w;
    }
#pragma unroll
    for (int off = 8; off > 0; off >>= 1) {
        p0 += __shfl_down_sync(0xffffffffu, p0, off, 16);
        p1 += __shfl_down_sync(0xffffffffu, p1, off, 16);
        p2 += __shfl_down_sync(0xffffffffu, p2, off, 16);
    }
    if (f4 == 0) {
        int b = bn / Nn, n = bn % Nn;
        out[b * 3 * Nn + 0 * Nn + n] = p0 + outb[0];
        out[b * 3 * Nn + 1 * Nn + n] = p1 + outb[1];
        out[b * 3 * Nn + 2 * Nn + n] = p2 + outb[2];
    }
}

// ---------------- launch ----------------------------------------------------
extern "C" void kernel_launch(void* const* d_in, const int* in_sizes, int n_in,
                              void* d_out, int out_size)
{
    const float* x     = (const float*)d_in[0];
    const float* adj   = (const float*)d_in[1];   // int32 payload, cast inside prep
    const float* Wih0  = (const float*)d_in[2];
    const float* Whh0  = (const float*)d_in[3];
    const float* bih0  = (const float*)d_in[4];
    const float* bhh0  = (const float*)d_in[5];
    const float* Wih1  = (const float*)d_in[6];
    const float* Whh1  = (const float*)d_in[7];
    const float* bih1  = (const float*)d_in[8];
    const float* bhh1  = (const float*)d_in[9];
    const float* g0W   = (const float*)d_in[10];
    const float* g0as  = (const float*)d_in[11];
    const float* g0ad  = (const float*)d_in[12];
    const float* g1W   = (const float*)d_in[13];
    const float* g1as  = (const float*)d_in[14];
    const float* g1ad  = (const float*)d_in[15];
    const float* outW  = (const float*)d_in[16];
    const float* outb  = (const float*)d_in[17];
    float* out = (float*)d_out;

    prep_kernel<<<(Nn * NW + 255) / 256, 256>>>(adj, Whh0, bih0, bhh0,
                                                Wih1, Whh1, bih1, bhh1, g0W, g1W);
    lstm_kernel<<<BN / SPB, 128>>>(x, Wih0);

    dim3 agrid((Nn + TI - 1) / TI, Bb, ZCH);

    gat_proj_kernel<0><<<BN / 4, 256>>>(g0as, g0ad);
    gat_attn_kernel<<<agrid, 128>>>();
    gat_combine_kernel<<<(BN * 16 + 255) / 256, 256>>>();

    gat_proj_kernel<1><<<BN / 4, 256>>>(g1as, g1ad);
    gat_attn_kernel<<<agrid, 128>>>();
    gat_combine_out_kernel<<<(BN * 16 + 255) / 256, 256>>>(outW, outb, out);
}